// round 2
// baseline (speedup 1.0000x reference)
#include <cuda_runtime.h>
#include <stdint.h>

#define HH 1024
#define WW 2048
#define PS 16
#define STR 8
#define NHH 127
#define NWW 255
#define P_TOT (NHH * NWW)   /* 32385 */
#define MARGIN_F 1e-4f
#define WARPS_PER_BLK 8
#define FULL 0xffffffffu

__device__ double   g_loss_sum;
__device__ double   g_used;
__device__ int      g_mask_mode;   // 0 = uint8, 1 = float32, 2 = int32
__device__ unsigned g_done;

// ---------------------------------------------------------------------------
// One-warp mask-dtype detect + accumulator zeroing (runs every replay)
// ---------------------------------------------------------------------------
__global__ void detect_zero_kernel(const uint8_t* __restrict__ mask_raw) {
    const uint32_t* w = (const uint32_t*)mask_raw;
    const int lane = threadIdx.x;
    uint32_t acc_or = 0;
    bool gt1 = false;
    #pragma unroll
    for (int i = 0; i < 8; i++) {
        const uint32_t x = __ldg(w + lane + 32 * i);
        acc_or |= x;
        gt1 |= (x > 1u);
    }
    const bool big = (acc_or & 0xFEFEFEFEu) != 0;   // f32 pattern (0x3F800000)
    const unsigned bb = __ballot_sync(FULL, big);
    const unsigned bg = __ballot_sync(FULL, gt1);
    if (lane == 0) {
        g_mask_mode = bb ? 1 : (bg ? 0 : 2);        // f32 : u8 : i32
        g_loss_sum  = 0.0;
        g_used      = 0.0;
        g_done      = 0u;
    }
}

// ---------------------------------------------------------------------------
// Main kernel: one warp per patch, thread-major bitonic sort of 256 tokens.
//   element v = 8*lane + r ; token = (noise_bits & 0xFFFFFF00) | v (masked)
//                                  =  0xFF000000 | v             (unmasked)
// ---------------------------------------------------------------------------
__global__ __launch_bounds__(256) void patch_loss_kernel(
    const float* __restrict__ pred,
    const float* __restrict__ target,
    const uint8_t* __restrict__ mask_raw,
    const float* __restrict__ noise,
    float* __restrict__ out)
{
    __shared__ float   s_pp[WARPS_PER_BLK][256];
    __shared__ float   s_tp[WARPS_PER_BLK][256];
    __shared__ uint8_t s_m [WARPS_PER_BLK][256];
    __shared__ float   s_blk_loss;
    __shared__ float   s_blk_cnt;

    const int wid  = threadIdx.x >> 5;
    const int lane = threadIdx.x & 31;
    if (threadIdx.x == 0) { s_blk_loss = 0.f; s_blk_cnt = 0.f; }
    __syncthreads();

    const int p = blockIdx.x * WARPS_PER_BLK + wid;
    if (p < P_TOT) {
        const int pi = p / NWW;
        const int pj = p - pi * NWW;
        const int br = pi * STR;
        const int bc = pj * STR;
        const int mode = g_mask_mode;

        const int e0 = lane << 3;              // first element of this thread
        const int a  = lane >> 1;              // patch row
        const int cb = (lane & 1) << 3;        // patch col base
        const int gbase = (br + a) * WW + bc + cb;

        // ---- vectorized loads: 8 consecutive pixels / noise values ----
        const float4 p0 = __ldg((const float4*)(pred + gbase));
        const float4 p1 = __ldg((const float4*)(pred + gbase) + 1);
        const float4 t0 = __ldg((const float4*)(target + gbase));
        const float4 t1 = __ldg((const float4*)(target + gbase) + 1);
        *(float4*)&s_pp[wid][e0]     = p0;
        *(float4*)&s_pp[wid][e0 + 4] = p1;
        *(float4*)&s_tp[wid][e0]     = t0;
        *(float4*)&s_tp[wid][e0 + 4] = t1;

        bool mk[8];
        if (mode == 0) {
            const uint2 mb = __ldg((const uint2*)(mask_raw + gbase));
            #pragma unroll
            for (int r = 0; r < 4; r++) mk[r]     = ((mb.x >> (8 * r)) & 0xFFu) != 0;
            #pragma unroll
            for (int r = 0; r < 4; r++) mk[4 + r] = ((mb.y >> (8 * r)) & 0xFFu) != 0;
        } else if (mode == 1) {
            const float4 m0 = __ldg((const float4*)((const float*)mask_raw + gbase));
            const float4 m1 = __ldg((const float4*)((const float*)mask_raw + gbase) + 1);
            mk[0] = m0.x != 0.f; mk[1] = m0.y != 0.f; mk[2] = m0.z != 0.f; mk[3] = m0.w != 0.f;
            mk[4] = m1.x != 0.f; mk[5] = m1.y != 0.f; mk[6] = m1.z != 0.f; mk[7] = m1.w != 0.f;
        } else {
            const uint4 m0 = __ldg((const uint4*)((const uint32_t*)mask_raw + gbase));
            const uint4 m1 = __ldg((const uint4*)((const uint32_t*)mask_raw + gbase) + 1);
            mk[0] = m0.x != 0; mk[1] = m0.y != 0; mk[2] = m0.z != 0; mk[3] = m0.w != 0;
            mk[4] = m1.x != 0; mk[5] = m1.y != 0; mk[6] = m1.z != 0; mk[7] = m1.w != 0;
        }

        const float4 n0 = __ldg((const float4*)(noise + (size_t)p * 256 + e0));
        const float4 n1 = __ldg((const float4*)(noise + (size_t)p * 256 + e0) + 1);
        float nz[8] = {n0.x, n0.y, n0.z, n0.w, n1.x, n1.y, n1.z, n1.w};

        uint32_t tok[8];
        #pragma unroll
        for (int r = 0; r < 8; r++) {
            const uint32_t kb = __float_as_uint(nz[r]) & 0xFFFFFF00u;
            tok[r] = mk[r] ? (kb | (uint32_t)(e0 + r))
                           : (0xFF000000u | (uint32_t)(e0 + r));
        }

        // ---- masked-index list: per-thread popcount + warp exclusive scan ----
        int cnt = 0;
        #pragma unroll
        for (int r = 0; r < 8; r++) cnt += mk[r] ? 1 : 0;
        int inc = cnt;
        #pragma unroll
        for (int o = 1; o < 32; o <<= 1) {
            const int t = __shfl_up_sync(FULL, inc, o);
            if (lane >= o) inc += t;
        }
        int run = inc - cnt;
        #pragma unroll
        for (int r = 0; r < 8; r++)
            if (mk[r]) s_m[wid][run++] = (uint8_t)(e0 + r);
        const int K = __shfl_sync(FULL, inc, 31);
        __syncwarp();

        // ---- bitonic sort, ascending, thread-major (v = 8*lane + r) ----
        #pragma unroll
        for (int k = 2; k <= 256; k <<= 1) {
            #pragma unroll
            for (int j = k >> 1; j >= 1; j >>= 1) {
                if (j >= 8) {
                    const int jl = j >> 3;
                    const bool takeMin =
                        (((lane & (k >> 3)) == 0) == ((lane & jl) == 0));
                    #pragma unroll
                    for (int r = 0; r < 8; r++) {
                        const uint32_t o = __shfl_xor_sync(FULL, tok[r], jl);
                        tok[r] = takeMin ? min(tok[r], o) : max(tok[r], o);
                    }
                } else {
                    #pragma unroll
                    for (int r = 0; r < 8; r++) {
                        if ((r & j) == 0) {
                            const int r2 = r | j;
                            const bool up = (k < 8) ? ((r & k) == 0)
                                                    : ((lane & (k >> 3)) == 0);
                            const uint32_t A = tok[r], B = tok[r2];
                            const uint32_t mn = min(A, B), mx = max(A, B);
                            tok[r]  = up ? mn : mx;
                            tok[r2] = up ? mx : mn;
                        }
                    }
                }
            }
        }
        __syncwarp();

        // ---- hinge epilogue: rank v < K pairs (s_m[v], sorted_idx[v]) ----
        float loss = 0.f;
        int   hit  = 0;
        #pragma unroll
        for (int r = 0; r < 8; r++) {
            const int v = e0 + r;
            if (v < K) {
                const int bI = (int)(tok[r] & 0xFFu);
                const int aI = (int)s_m[wid][v];
                const float dt = s_tp[wid][aI] - s_tp[wid][bI];
                const float dp = s_pp[wid][aI] - s_pp[wid][bI] + MARGIN_F;
                const int st = (dt > 0.f) - (dt < 0.f);
                const int sp = (dp > 0.f) - (dp < 0.f);
                if (st != sp) { hit++; loss += fabsf(dp); }
            }
        }
        #pragma unroll
        for (int o = 16; o; o >>= 1) {
            loss += __shfl_xor_sync(FULL, loss, o);
            hit  += __shfl_xor_sync(FULL, hit,  o);
        }
        if (lane == 0 && K > 0) {
            atomicAdd(&s_blk_loss, loss / (float)hit);
            atomicAdd(&s_blk_cnt, 1.0f);
        }
    }
    __syncthreads();

    // ---- block -> global accumulation; last block finalizes out[0] ----
    if (threadIdx.x == 0) {
        atomicAdd(&g_loss_sum, (double)s_blk_loss);
        atomicAdd(&g_used,     (double)s_blk_cnt);
        __threadfence();
        const unsigned ticket = atomicAdd(&g_done, 1u);
        if (ticket == gridDim.x - 1) {
            const double ls = atomicAdd(&g_loss_sum, 0.0);
            const double us = atomicAdd(&g_used, 0.0);
            out[0] = (float)(ls / us);
        }
    }
}

// ---------------------------------------------------------------------------
extern "C" void kernel_launch(void* const* d_in, const int* in_sizes, int n_in,
                              void* d_out, int out_size) {
    const float*   pred   = (const float*)d_in[0];
    const float*   target = (const float*)d_in[1];
    const uint8_t* mask   = (const uint8_t*)d_in[2];
    const float*   noise  = (const float*)d_in[3];

    detect_zero_kernel<<<1, 32>>>(mask);
    const int nblocks = (P_TOT + WARPS_PER_BLK - 1) / WARPS_PER_BLK;
    patch_loss_kernel<<<nblocks, 256>>>(pred, target, mask, noise, (float*)d_out);
}

// round 3
// speedup vs baseline: 1.0854x; 1.0854x over previous
#include <cuda_runtime.h>
#include <stdint.h>

#define HH 1024
#define WW 2048
#define PS 16
#define STR 8
#define NHH 127
#define NWW 255
#define P_TOT (NHH * NWW)   /* 32385 */
#define MARGIN_F 1e-4f
#define WARPS_PER_BLK 8
#define NBLOCKS ((P_TOT + WARPS_PER_BLK - 1) / WARPS_PER_BLK)
#define FULL 0xffffffffu

__device__ double   g_loss_sum = 0.0;
__device__ double   g_used     = 0.0;
__device__ unsigned g_done     = 0u;

// ---------------------------------------------------------------------------
// Single kernel: one warp per patch. Warp 0 of each block also derives the
// mask dtype (0=u8, 1=f32, 2=i32) from the first 1KB of the mask buffer.
// Lane-major bitonic sort of 256 tokens (v = lane + 32*r):
//   token = (noise_bits & 0xFFFFFF00) | elem_idx  (masked)
//         =  0xFF000000 | elem_idx                (unmasked -> sorts last)
// ---------------------------------------------------------------------------
__global__ __launch_bounds__(256) void patch_loss_kernel(
    const float* __restrict__ pred,
    const float* __restrict__ target,
    const uint8_t* __restrict__ mask_raw,
    const float* __restrict__ noise,
    float* __restrict__ out)
{
    __shared__ float   s_pp[WARPS_PER_BLK][256];
    __shared__ float   s_tp[WARPS_PER_BLK][256];
    __shared__ uint8_t s_m [WARPS_PER_BLK][256];
    __shared__ float   s_blk_loss;
    __shared__ float   s_blk_cnt;
    __shared__ int     s_mode;

    const int wid  = threadIdx.x >> 5;
    const int lane = threadIdx.x & 31;

    if (threadIdx.x == 0) { s_blk_loss = 0.f; s_blk_cnt = 0.f; }
    if (wid == 0) {
        // mask dtype detection on the first 256 words (same for all blocks)
        const uint32_t* w = (const uint32_t*)mask_raw;
        uint32_t acc_or = 0;
        bool gt1 = false;
        #pragma unroll
        for (int i = 0; i < 8; i++) {
            const uint32_t x = __ldg(w + lane + 32 * i);
            acc_or |= x;
            gt1 |= (x > 1u);
        }
        const unsigned bb = __ballot_sync(FULL, (acc_or & 0xFEFEFEFEu) != 0);
        const unsigned bg = __ballot_sync(FULL, gt1);
        if (lane == 0) s_mode = bb ? 1 : (bg ? 0 : 2);   // f32 : u8 : i32
    }
    __syncthreads();

    const int p = blockIdx.x * WARPS_PER_BLK + wid;
    if (p < P_TOT) {
        const int pi = p / NWW;
        const int pj = p - pi * NWW;
        const int br = pi * STR;
        const int bc = pj * STR;
        const int mode = s_mode;

        uint32_t tok[8];
        bool     mk[8];

        #pragma unroll
        for (int r = 0; r < 8; r++) {
            const int e  = lane + 32 * r;
            const int a  = e >> 4;
            const int b  = e & 15;
            const int gi = (br + a) * WW + (bc + b);
            const float pv = __ldg(pred + gi);
            const float tv = __ldg(target + gi);
            s_pp[wid][e] = pv;
            s_tp[wid][e] = tv;
            bool m;
            if (mode == 0)      m = mask_raw[gi] != 0;
            else if (mode == 1) m = ((const float*)mask_raw)[gi] != 0.0f;
            else                m = ((const int*)mask_raw)[gi] != 0;
            mk[r] = m;
            const float nz = __ldg(noise + (size_t)p * 256 + e);
            const uint32_t kb = __float_as_uint(nz);
            tok[r] = m ? ((kb & 0xFFFFFF00u) | (uint32_t)e)
                       : (0xFF000000u | (uint32_t)e);
        }

        // index-ranks of masked elements via ballots; scatter masked-index list
        const uint32_t lt = (1u << lane) - 1u;
        int pre = 0;
        #pragma unroll
        for (int r = 0; r < 8; r++) {
            const uint32_t bl = __ballot_sync(FULL, mk[r]);
            const int rk = pre + __popc(bl & lt);
            if (mk[r]) s_m[wid][rk] = (uint8_t)(lane + 32 * r);
            pre += __popc(bl);
        }
        const int K = pre;
        __syncwarp();

        // ---- bitonic sort, ascending; position v = lane + 32*r ----
        #pragma unroll
        for (int k = 2; k <= 256; k <<= 1) {
            #pragma unroll
            for (int j = k >> 1; j >= 1; j >>= 1) {
                if (j >= 32) {
                    const int jr = j >> 5;
                    #pragma unroll
                    for (int r = 0; r < 8; r++) {
                        if ((r & jr) == 0) {
                            const int r2 = r | jr;
                            const bool up = (((lane + 32 * r) & k) == 0);
                            const uint32_t A = tok[r], B = tok[r2];
                            const uint32_t mn = min(A, B), mx = max(A, B);
                            tok[r]  = up ? mn : mx;
                            tok[r2] = up ? mx : mn;
                        }
                    }
                } else {
                    #pragma unroll
                    for (int r = 0; r < 8; r++) {
                        const int v = lane + 32 * r;
                        const uint32_t other = __shfl_xor_sync(FULL, tok[r], j);
                        const bool takeMin = (((v & k) == 0) == ((v & j) == 0));
                        const uint32_t mn = min(tok[r], other), mx = max(tok[r], other);
                        tok[r] = takeMin ? mn : mx;
                    }
                }
            }
        }
        __syncwarp();

        // ---- hinge epilogue: rank v < K pairs (s_m[v], sorted_idx[v]) ----
        float loss = 0.f;
        int   cnt  = 0;
        #pragma unroll
        for (int r = 0; r < 8; r++) {
            const int v = lane + 32 * r;
            if (v < K) {
                const int bI = (int)(tok[r] & 0xFFu);
                const int aI = (int)s_m[wid][v];
                const float dt = s_tp[wid][aI] - s_tp[wid][bI];
                const float dp = s_pp[wid][aI] - s_pp[wid][bI] + MARGIN_F;
                const int st = (dt > 0.f) - (dt < 0.f);
                const int sp = (dp > 0.f) - (dp < 0.f);
                if (st != sp) { cnt++; loss += fabsf(dp); }
            }
        }
        #pragma unroll
        for (int o = 16; o; o >>= 1) {
            loss += __shfl_xor_sync(FULL, loss, o);
            cnt  += __shfl_xor_sync(FULL, cnt,  o);
        }
        if (lane == 0 && K > 0) {
            atomicAdd(&s_blk_loss, loss / (float)cnt);
            atomicAdd(&s_blk_cnt, 1.0f);
        }
    }
    __syncthreads();

    // ---- block -> global accumulation; last block finalizes + resets ----
    if (threadIdx.x == 0) {
        atomicAdd(&g_loss_sum, (double)s_blk_loss);
        atomicAdd(&g_used,     (double)s_blk_cnt);
        __threadfence();
        const unsigned ticket = atomicAdd(&g_done, 1u);
        if (ticket == (unsigned)(gridDim.x - 1)) {
            const double ls = atomicAdd(&g_loss_sum, 0.0);
            const double us = atomicAdd(&g_used, 0.0);
            out[0] = (float)(ls / us);
            // reset for the next graph replay (all blocks are done here)
            g_loss_sum = 0.0;
            g_used     = 0.0;
            __threadfence();
            g_done = 0u;
        }
    }
}

// ---------------------------------------------------------------------------
extern "C" void kernel_launch(void* const* d_in, const int* in_sizes, int n_in,
                              void* d_out, int out_size) {
    const float*   pred   = (const float*)d_in[0];
    const float*   target = (const float*)d_in[1];
    const uint8_t* mask   = (const uint8_t*)d_in[2];
    const float*   noise  = (const float*)d_in[3];

    patch_loss_kernel<<<NBLOCKS, 256>>>(pred, target, mask, noise, (float*)d_out);
}